// round 9
// baseline (speedup 1.0000x reference)
#include <cuda_runtime.h>
#include <cuda_bf16.h>
#include <stdint.h>
#include <math.h>

#define Bc   4
#define Nc   2000
#define Cc   128
#define hc   128
#define wc   128
#define BNc  (Bc*Nc)          // 8000
#define Pc   29
#define NGc  80
#define NCAND (Pc+NGc)        // 109
#define NCOLS (1+NGc+BNc)     // 8081
#define BN_PAD 8064           // 63*128

// ---------------- scratch (device globals; no allocations allowed) ----------
__device__ float g_feat0T[(size_t)Bc*hc*wc*Cc];   // [B][h][w][C]
__device__ float g_feat1T[(size_t)Bc*hc*wc*Cc];
__device__ float g_vf0 [(size_t)BN_PAD*Cc];       // l2-normalized query feats (fp32)
__device__ __nv_bfloat16 g_Ah[(size_t)BN_PAD*Cc]; // vf0 hi
__device__ __nv_bfloat16 g_Al[(size_t)BN_PAD*Cc]; // vf0 lo
__device__ __nv_bfloat16 g_Bh[(size_t)BN_PAD*Cc]; // dist hi
__device__ __nv_bfloat16 g_Bl[(size_t)BN_PAD*Cc]; // dist lo
__device__ float g_vp1[BNc*2];                    // (y,x) of pos1[:N]
__device__ float g_vp2[BNc*2];                    // (y,x) of pos1[M-N:]
__device__ float g_qc0[BNc];
__device__ int   g_off[NCAND*2];                  // (dy,dx); 0..28 pos, 29..108 neg

// ---------------- offset generation (exact Python loop order) ---------------
__global__ void k_init_off() {
    if (blockIdx.x == 0 && threadIdx.x == 0) {
        int np = 0, nn = 0;
        for (int dx = -7; dx <= 7; dx++)
            for (int dy = -7; dy <= 7; dy++) {
                int d2 = dx*dx + dy*dy;
                if (d2 <= 9)            { g_off[np*2] = dy; g_off[np*2+1] = dx; np++; }
                else if (d2 >= 25 && d2 <= 49) { g_off[(Pc+nn)*2] = dy; g_off[(Pc+nn)*2+1] = dx; nn++; }
            }
    }
}

// ---------------- transpose [B,C,h,w] -> [B,h,w,C] ---------------------------
__global__ void k_transpose(const float* __restrict__ in, int which) {
    __shared__ float tile[32][33];
    float* out = which ? g_feat1T : g_feat0T;
    int b = blockIdx.z / hc, y = blockIdx.z % hc;
    const float* src = in + ((size_t)b*Cc*hc + y)*wc;
    float*       dst = out + (((size_t)b*hc + y)*wc)*Cc;
    int x0 = blockIdx.x * 32, c0 = blockIdx.y * 32;
    #pragma unroll
    for (int i = threadIdx.y; i < 32; i += 8)
        tile[i][threadIdx.x] = src[(size_t)(c0+i)*hc*wc + x0 + threadIdx.x];
    __syncthreads();
    #pragma unroll
    for (int i = threadIdx.y; i < 32; i += 8)
        dst[(size_t)(x0+i)*Cc + c0 + threadIdx.x] = tile[threadIdx.x][i];
}

// ---------------- helpers ----------------------------------------------------
__device__ __forceinline__ float4 bilin4(const float* __restrict__ base,
                                         float y, float x, int lane) {
    int yi = (int)y, xi = (int)x;
    float fy = y - yi, fx = x - xi;
    const float* p = base + (size_t)(yi*wc + xi)*Cc + lane*4;
    float4 a = *(const float4*)p;
    float4 b = *(const float4*)(p + Cc);
    float4 c = *(const float4*)(p + (size_t)wc*Cc);
    float4 d = *(const float4*)(p + (size_t)wc*Cc + Cc);
    float w00 = (1.f-fy)*(1.f-fx), w01 = (1.f-fy)*fx;
    float w10 = fy*(1.f-fx),       w11 = fy*fx;
    float4 r;
    r.x = w00*a.x + w01*b.x + w10*c.x + w11*d.x;
    r.y = w00*a.y + w01*b.y + w10*c.y + w11*d.y;
    r.z = w00*a.z + w01*b.z + w10*c.z + w11*d.z;
    r.w = w00*a.w + w01*b.w + w10*c.w + w11*d.w;
    return r;
}

__device__ __forceinline__ float bilin1(const float* __restrict__ img, float y, float x) {
    int yi = (int)y, xi = (int)x;
    float fy = y - yi, fx = x - xi;
    const float* p = img + yi*wc + xi;
    float a = p[0], b = p[1], c = p[wc], d = p[wc+1];
    return (1.f-fy)*((1.f-fx)*a + fx*b) + fy*((1.f-fx)*c + fx*d);
}

__device__ __forceinline__ float wsum(float v) {
    #pragma unroll
    for (int o = 16; o; o >>= 1) v += __shfl_xor_sync(0xffffffffu, v, o);
    return v;
}

__device__ __forceinline__ void split_store(float4 v, __nv_bfloat16* bh,
                                            __nv_bfloat16* bl, int lane) {
    float f[4] = {v.x, v.y, v.z, v.w};
    __nv_bfloat16 h[4], l[4];
    #pragma unroll
    for (int i = 0; i < 4; i++) {
        h[i] = __float2bfloat16(f[i]);
        l[i] = __float2bfloat16(f[i] - __bfloat162float(h[i]));
    }
    *(uint2*)(bh + lane*4) = *(uint2*)h;
    *(uint2*)(bl + lane*4) = *(uint2*)l;
}

// ---------------- prep: vf0, dist(hi/lo), qconf0, positions ------------------
__global__ void k_prep(const int* __restrict__ pos0, const int* __restrict__ pos1,
                       const float* __restrict__ conf0, int M) {
    int t = blockIdx.x*blockDim.x + threadIdx.x;
    int gid = t >> 5;
    if (gid >= BNc) return;
    int lane = t & 31;
    int b = gid / Nc, n = gid - b*Nc;
    const float* f0b = g_feat0T + (size_t)b*hc*wc*Cc;
    const float* f1b = g_feat1T + (size_t)b*hc*wc*Cc;
    int2 p0 = ((const int2*)pos0)[(size_t)b*M + n];
    int2 p1 = ((const int2*)pos1)[(size_t)b*M + n];
    int2 p2 = ((const int2*)pos1)[(size_t)b*M + (M - Nc) + n];

    float y0f = p0.x*0.25f, x0f = p0.y*0.25f;
    float4 v = bilin4(f0b, y0f, x0f, lane);
    float ss = wsum(v.x*v.x + v.y*v.y + v.z*v.z + v.w*v.w);
    float inv = 1.f / fmaxf(sqrtf(ss), 1e-12f);
    v.x*=inv; v.y*=inv; v.z*=inv; v.w*=inv;
    ((float4*)(g_vf0 + (size_t)gid*Cc))[lane] = v;
    split_store(v, g_Ah + (size_t)gid*Cc, g_Al + (size_t)gid*Cc, lane);

    float y2f = p2.x*0.25f, x2f = p2.y*0.25f;
    float4 u = bilin4(f1b, y2f, x2f, lane);
    float ss2 = wsum(u.x*u.x + u.y*u.y + u.z*u.z + u.w*u.w);
    float inv2 = 1.f / fmaxf(sqrtf(ss2), 1e-12f);
    u.x*=inv2; u.y*=inv2; u.z*=inv2; u.w*=inv2;
    split_store(u, g_Bh + (size_t)gid*Cc, g_Bl + (size_t)gid*Cc, lane);

    if (lane == 0) {
        g_qc0[gid] = bilin1(conf0 + (size_t)b*hc*wc, y0f, x0f);
        g_vp1[gid*2]   = (float)p1.x; g_vp1[gid*2+1] = (float)p1.y;
        g_vp2[gid*2]   = (float)p2.x; g_vp2[gid*2+1] = (float)p2.y;
    }
}

// ---------------- candidate scores (pos max + neg cols) + qconf + mask -------
__global__ void k_cand(const int* __restrict__ pos1, const float* __restrict__ conf1,
                       float* __restrict__ out_scores, float* __restrict__ out_mask,
                       float* __restrict__ out_qconf, int M) {
    __shared__ int soff[NCAND*2];
    for (int i = threadIdx.x; i < NCAND*2; i += blockDim.x) soff[i] = g_off[i];
    __syncthreads();

    int t = blockIdx.x*blockDim.x + threadIdx.x;
    int gid = t >> 5;
    if (gid >= BNc) return;
    int lane = t & 31;
    int b = gid / Nc, n = gid - b*Nc;
    int2 p1 = ((const int2*)pos1)[(size_t)b*M + n];
    const float* f1b = g_feat1T + (size_t)b*hc*wc*Cc;
    float4 q = ((const float4*)(g_vf0 + (size_t)gid*Cc))[lane];
    float* srow = out_scores + (size_t)gid*NCOLS;

    float best = -1e30f; int bestk = 0;
    for (int k = 0; k < NCAND; k++) {
        int dy = soff[2*k], dx = soff[2*k+1];
        float cy = (p1.x + dy)*0.25f, cx = (p1.y + dx)*0.25f;
        float4 fv = bilin4(f1b, cy, cx, lane);
        float dot = fv.x*q.x + fv.y*q.y + fv.z*q.z + fv.w*q.w;
        float ss  = fv.x*fv.x + fv.y*fv.y + fv.z*fv.z + fv.w*fv.w;
        #pragma unroll
        for (int o = 16; o; o >>= 1) {
            dot += __shfl_xor_sync(0xffffffffu, dot, o);
            ss  += __shfl_xor_sync(0xffffffffu, ss,  o);
        }
        float score = dot / fmaxf(sqrtf(ss), 1e-12f);
        if (k < Pc) { if (score > best) { best = score; bestk = k; } }
        else if (lane == 0) srow[1 + (k - Pc)] = score;
    }
    if (lane == 0) {
        srow[0] = best;
        int sy = p1.x + soff[2*bestk], sx = p1.y + soff[2*bestk+1];
        float q1 = bilin1(conf1 + (size_t)b*hc*wc, sy*0.25f, sx*0.25f);
        out_qconf[gid] = 0.5f*(g_qc0[gid] + q1);
        out_mask[gid]  = 1.0f;
    }
}

// ---------------- dscores: mma.sync split-bf16 GEMM 128x128 (K_eff=384) ------
// smem layout (bytes):
//   [0)      rpy/rpx/cpy/cpx float[128] each, rbb/cbb int[128]  (3072 B)
//   tiles: Ah, Al, Bh, Bl : 128 rows x 136 bf16 (pad 8) = 34816 B each
//   Ds slab: 32 x 132 f32 = 16896 B
#define LDT  136                 // bf16 leading dim of smem tiles
#define SM_ARR  0
#define SM_AH   3072
#define SM_AL   (SM_AH + 128*LDT*2)
#define SM_BH   (SM_AL + 128*LDT*2)
#define SM_BL   (SM_BH + 128*LDT*2)
#define SM_DS   (SM_BL + 128*LDT*2)
#define SM_TOTAL (SM_DS + 32*132*4)   // 159232

__device__ __forceinline__ void mma16816(float* c, const uint32_t* a, const uint32_t* b) {
    asm volatile(
        "mma.sync.aligned.m16n8k16.row.col.f32.bf16.bf16.f32 "
        "{%0,%1,%2,%3}, {%4,%5,%6,%7}, {%8,%9}, {%0,%1,%2,%3};"
        : "+f"(c[0]), "+f"(c[1]), "+f"(c[2]), "+f"(c[3])
        : "r"(a[0]), "r"(a[1]), "r"(a[2]), "r"(a[3]), "r"(b[0]), "r"(b[1]));
}

__global__ void __launch_bounds__(256, 1) k_gemm_mma(float* __restrict__ out_scores) {
    extern __shared__ char sm[];
    int tid = threadIdx.x, wid = tid >> 5, lane = tid & 31;
    int warp_m = wid & 3, warp_n = wid >> 2;       // 4 x 2 warps, warp tile 32x64
    int i0 = blockIdx.y * 128, j0 = blockIdx.x * 128;

    float* rpy = (float*)(sm + SM_ARR);
    float* rpx = rpy + 128;
    float* cpy = rpx + 128;
    float* cpx = cpy + 128;
    int*   rbb = (int*)(cpx + 128);
    int*   cbb = rbb + 128;
    float* Ds  = (float*)(sm + SM_DS);

    if (tid < 128) {
        int gi = i0 + tid;
        if (gi < BNc) { rpy[tid] = g_vp1[2*gi]; rpx[tid] = g_vp1[2*gi+1]; rbb[tid] = gi / Nc; }
        else          { rpy[tid] = 1e9f; rpx[tid] = 1e9f; rbb[tid] = -1; }
        int gj = j0 + tid;
        if (gj < BNc) { cpy[tid] = g_vp2[2*gj]; cpx[tid] = g_vp2[2*gj+1]; cbb[tid] = gj / Nc; }
        else          { cpy[tid] = -1e9f; cpx[tid] = -1e9f; cbb[tid] = -2; }
    }

    // load 4 tiles: 128 rows x 128 bf16 each, row stride LDT
    {
        int row8 = tid >> 4, c16 = tid & 15;     // 16 rows per 256-thread sweep
        #pragma unroll
        for (int tile = 0; tile < 4; tile++) {
            const __nv_bfloat16* g;
            char* base;
            int r0;
            if      (tile == 0) { g = g_Ah; r0 = i0; base = sm + SM_AH; }
            else if (tile == 1) { g = g_Al; r0 = i0; base = sm + SM_AL; }
            else if (tile == 2) { g = g_Bh; r0 = j0; base = sm + SM_BH; }
            else                { g = g_Bl; r0 = j0; base = sm + SM_BL; }
            #pragma unroll
            for (int it = 0; it < 8; it++) {
                int row = it * 16 + row8;
                *(uint4*)(base + row * (LDT*2) + c16 * 16) =
                    *(const uint4*)(g + (size_t)(r0 + row) * Cc + c16 * 8);
            }
        }
    }
    __syncthreads();

    float acc[2][8][4];
    #pragma unroll
    for (int mt = 0; mt < 2; mt++)
        #pragma unroll
        for (int nt = 0; nt < 8; nt++)
            #pragma unroll
            for (int q = 0; q < 4; q++) acc[mt][nt][q] = 0.f;

    const uint32_t* As32[3] = { (const uint32_t*)(sm + SM_AH), (const uint32_t*)(sm + SM_AH),
                                (const uint32_t*)(sm + SM_AL) };
    const uint32_t* Bs32[3] = { (const uint32_t*)(sm + SM_BH), (const uint32_t*)(sm + SM_BL),
                                (const uint32_t*)(sm + SM_BH) };
    const int LDW = LDT / 2;   // 68 32-bit words per row

    int qrow = lane >> 2, qk = lane & 3;
    #pragma unroll
    for (int pass = 0; pass < 3; pass++) {
        const uint32_t* A32 = As32[pass];
        const uint32_t* B32 = Bs32[pass];
        #pragma unroll
        for (int ks = 0; ks < 8; ks++) {
            int kw = ks * 8 + qk;
            uint32_t a[2][4], b[8][2];
            #pragma unroll
            for (int mt = 0; mt < 2; mt++) {
                int r = warp_m * 32 + mt * 16 + qrow;
                a[mt][0] = A32[r * LDW + kw];
                a[mt][1] = A32[(r + 8) * LDW + kw];
                a[mt][2] = A32[r * LDW + kw + 4];
                a[mt][3] = A32[(r + 8) * LDW + kw + 4];
            }
            #pragma unroll
            for (int nt = 0; nt < 8; nt++) {
                int n = warp_n * 64 + nt * 8 + qrow;
                b[nt][0] = B32[n * LDW + kw];
                b[nt][1] = B32[n * LDW + kw + 4];
            }
            #pragma unroll
            for (int mt = 0; mt < 2; mt++)
                #pragma unroll
                for (int nt = 0; nt < 8; nt++)
                    mma16816(acc[mt][nt], a[mt], b[nt]);
        }
    }
    __syncthreads();

    // epilogue: 4 slabs of 32 rows; stage in smem, masked coalesced write
    #pragma unroll
    for (int s = 0; s < 4; s++) {
        if (warp_m == s) {
            #pragma unroll
            for (int mt = 0; mt < 2; mt++) {
                int rr = mt * 16 + qrow;
                #pragma unroll
                for (int nt = 0; nt < 8; nt++) {
                    int cc = warp_n * 64 + nt * 8 + 2 * qk;
                    *(float2*)&Ds[rr * 132 + cc] =
                        make_float2(acc[mt][nt][0], acc[mt][nt][1]);
                    *(float2*)&Ds[(rr + 8) * 132 + cc] =
                        make_float2(acc[mt][nt][2], acc[mt][nt][3]);
                }
            }
        }
        __syncthreads();
        for (int rr = wid; rr < 32; rr += 8) {
            int lrow = s * 32 + rr;
            int gi = i0 + lrow;
            if (gi < BNc) {
                float py = rpy[lrow], px = rpx[lrow];
                int bi = rbb[lrow];
                float* orow = out_scores + (size_t)gi * NCOLS + 1 + NGc + j0;
                #pragma unroll
                for (int cb = 0; cb < 128; cb += 32) {
                    int j = cb + lane, gj = j0 + j;
                    if (gj < BNc) {
                        float v = Ds[rr * 132 + j];
                        float dy = cpy[j] - py, dx = cpx[j] - px;
                        if (bi == cbb[j] && dy*dy + dx*dx < 25.f) v = 0.f;
                        orow[j] = v;
                    }
                }
            }
        }
        __syncthreads();
    }
}

// ---------------- gt fill ----------------------------------------------------
__global__ void k_zero_gt(float4* __restrict__ gt4) {
    size_t n4 = (size_t)BNc * NCOLS / 4;
    size_t stride = (size_t)gridDim.x * blockDim.x;
    float4 z = make_float4(0.f, 0.f, 0.f, 0.f);
    for (size_t i = (size_t)blockIdx.x*blockDim.x + threadIdx.x; i < n4; i += stride)
        gt4[i] = z;
}
__global__ void k_ones_gt(float* __restrict__ gt) {
    int i = blockIdx.x*blockDim.x + threadIdx.x;
    if (i < BNc) gt[(size_t)i * NCOLS] = 1.f;
}

// ---------------- launch -----------------------------------------------------
extern "C" void kernel_launch(void* const* d_in, const int* in_sizes, int n_in,
                              void* d_out, int out_size) {
    const float* feat0 = (const float*)d_in[0];
    const float* feat1 = (const float*)d_in[1];
    const float* conf0 = (const float*)d_in[2];
    const float* conf1 = (const float*)d_in[3];
    const int*   pos0  = (const int*)d_in[4];
    const int*   pos1  = (const int*)d_in[5];
    int M = in_sizes[4] / (2 * Bc);   // 2500

    float* out        = (float*)d_out;
    float* out_scores = out;
    float* out_gt     = out + (size_t)BNc*NCOLS;
    float* out_mask   = out_gt + (size_t)BNc*NCOLS;
    float* out_qconf  = out_mask + BNc;

    cudaFuncSetAttribute(k_gemm_mma, cudaFuncAttributeMaxDynamicSharedMemorySize, SM_TOTAL);

    k_init_off<<<1, 1>>>();

    dim3 tb(32, 8), tg(wc/32, Cc/32, Bc*hc);
    k_transpose<<<tg, tb>>>(feat0, 0);
    k_transpose<<<tg, tb>>>(feat1, 1);

    k_prep<<<(BNc*32 + 255)/256, 256>>>(pos0, pos1, conf0, M);
    k_cand<<<(BNc*32 + 255)/256, 256>>>(pos1, conf1, out_scores, out_mask, out_qconf, M);

    dim3 gg(BN_PAD/128, BN_PAD/128);
    k_gemm_mma<<<gg, 256, SM_TOTAL>>>(out_scores);

    k_zero_gt<<<4096, 256>>>((float4*)out_gt);
    k_ones_gt<<<(BNc + 255)/256, 256>>>(out_gt);
}

// round 10
// speedup vs baseline: 1.0032x; 1.0032x over previous
#include <cuda_runtime.h>
#include <cuda_bf16.h>
#include <stdint.h>
#include <math.h>

#define Bc   4
#define Nc   2000
#define Cc   128
#define hc   128
#define wc   128
#define BNc  (Bc*Nc)          // 8000
#define Pc   29
#define NGc  80
#define NCAND (Pc+NGc)        // 109
#define NCOLS (1+NGc+BNc)     // 8081
#define BN_PAD 8064           // 63*128

// ---------------- scratch (device globals; no allocations allowed) ----------
__device__ float g_feat0T[(size_t)Bc*hc*wc*Cc];   // [B][h][w][C]
__device__ float g_feat1T[(size_t)Bc*hc*wc*Cc];
__device__ float g_vf0 [(size_t)BN_PAD*Cc];       // l2-normalized query feats (fp32)
__device__ __nv_bfloat16 g_Ah[(size_t)BN_PAD*Cc]; // vf0 hi
__device__ __nv_bfloat16 g_Al[(size_t)BN_PAD*Cc]; // vf0 lo
__device__ __nv_bfloat16 g_Bh[(size_t)BN_PAD*Cc]; // dist hi
__device__ __nv_bfloat16 g_Bl[(size_t)BN_PAD*Cc]; // dist lo
__device__ float g_vp1[BNc*2];                    // (y,x) of pos1[:N]
__device__ float g_vp2[BNc*2];                    // (y,x) of pos1[M-N:]
__device__ float g_qc0[BNc];
__device__ int   g_off[NCAND*2];                  // (dy,dx); 0..28 pos, 29..108 neg

// ---------------- offset generation (exact Python loop order) ---------------
__global__ void k_init_off() {
    if (blockIdx.x == 0 && threadIdx.x == 0) {
        int np = 0, nn = 0;
        for (int dx = -7; dx <= 7; dx++)
            for (int dy = -7; dy <= 7; dy++) {
                int d2 = dx*dx + dy*dy;
                if (d2 <= 9)            { g_off[np*2] = dy; g_off[np*2+1] = dx; np++; }
                else if (d2 >= 25 && d2 <= 49) { g_off[(Pc+nn)*2] = dy; g_off[(Pc+nn)*2+1] = dx; nn++; }
            }
    }
}

// ---------------- transpose [B,C,h,w] -> [B,h,w,C] ---------------------------
__global__ void k_transpose(const float* __restrict__ in, int which) {
    __shared__ float tile[32][33];
    float* out = which ? g_feat1T : g_feat0T;
    int b = blockIdx.z / hc, y = blockIdx.z % hc;
    const float* src = in + ((size_t)b*Cc*hc + y)*wc;
    float*       dst = out + (((size_t)b*hc + y)*wc)*Cc;
    int x0 = blockIdx.x * 32, c0 = blockIdx.y * 32;
    #pragma unroll
    for (int i = threadIdx.y; i < 32; i += 8)
        tile[i][threadIdx.x] = src[(size_t)(c0+i)*hc*wc + x0 + threadIdx.x];
    __syncthreads();
    #pragma unroll
    for (int i = threadIdx.y; i < 32; i += 8)
        dst[(size_t)(x0+i)*Cc + c0 + threadIdx.x] = tile[threadIdx.x][i];
}

// ---------------- helpers ----------------------------------------------------
__device__ __forceinline__ float4 bilin4(const float* __restrict__ base,
                                         float y, float x, int lane) {
    int yi = (int)y, xi = (int)x;
    float fy = y - yi, fx = x - xi;
    const float* p = base + (size_t)(yi*wc + xi)*Cc + lane*4;
    float4 a = *(const float4*)p;
    float4 b = *(const float4*)(p + Cc);
    float4 c = *(const float4*)(p + (size_t)wc*Cc);
    float4 d = *(const float4*)(p + (size_t)wc*Cc + Cc);
    float w00 = (1.f-fy)*(1.f-fx), w01 = (1.f-fy)*fx;
    float w10 = fy*(1.f-fx),       w11 = fy*fx;
    float4 r;
    r.x = w00*a.x + w01*b.x + w10*c.x + w11*d.x;
    r.y = w00*a.y + w01*b.y + w10*c.y + w11*d.y;
    r.z = w00*a.z + w01*b.z + w10*c.z + w11*d.z;
    r.w = w00*a.w + w01*b.w + w10*c.w + w11*d.w;
    return r;
}

__device__ __forceinline__ float bilin1(const float* __restrict__ img, float y, float x) {
    int yi = (int)y, xi = (int)x;
    float fy = y - yi, fx = x - xi;
    const float* p = img + yi*wc + xi;
    float a = p[0], b = p[1], c = p[wc], d = p[wc+1];
    return (1.f-fy)*((1.f-fx)*a + fx*b) + fy*((1.f-fx)*c + fx*d);
}

__device__ __forceinline__ float wsum(float v) {
    #pragma unroll
    for (int o = 16; o; o >>= 1) v += __shfl_xor_sync(0xffffffffu, v, o);
    return v;
}

__device__ __forceinline__ void split_store(float4 v, __nv_bfloat16* bh,
                                            __nv_bfloat16* bl, int lane) {
    float f[4] = {v.x, v.y, v.z, v.w};
    __nv_bfloat16 h[4], l[4];
    #pragma unroll
    for (int i = 0; i < 4; i++) {
        h[i] = __float2bfloat16(f[i]);
        l[i] = __float2bfloat16(f[i] - __bfloat162float(h[i]));
    }
    *(uint2*)(bh + lane*4) = *(uint2*)h;
    *(uint2*)(bl + lane*4) = *(uint2*)l;
}

// ---------------- prep: vf0, dist(hi/lo), qconf0, positions ------------------
__global__ void k_prep(const int* __restrict__ pos0, const int* __restrict__ pos1,
                       const float* __restrict__ conf0, int M) {
    int t = blockIdx.x*blockDim.x + threadIdx.x;
    int gid = t >> 5;
    if (gid >= BNc) return;
    int lane = t & 31;
    int b = gid / Nc, n = gid - b*Nc;
    const float* f0b = g_feat0T + (size_t)b*hc*wc*Cc;
    const float* f1b = g_feat1T + (size_t)b*hc*wc*Cc;
    int2 p0 = ((const int2*)pos0)[(size_t)b*M + n];
    int2 p1 = ((const int2*)pos1)[(size_t)b*M + n];
    int2 p2 = ((const int2*)pos1)[(size_t)b*M + (M - Nc) + n];

    float y0f = p0.x*0.25f, x0f = p0.y*0.25f;
    float4 v = bilin4(f0b, y0f, x0f, lane);
    float ss = wsum(v.x*v.x + v.y*v.y + v.z*v.z + v.w*v.w);
    float inv = 1.f / fmaxf(sqrtf(ss), 1e-12f);
    v.x*=inv; v.y*=inv; v.z*=inv; v.w*=inv;
    ((float4*)(g_vf0 + (size_t)gid*Cc))[lane] = v;
    split_store(v, g_Ah + (size_t)gid*Cc, g_Al + (size_t)gid*Cc, lane);

    float y2f = p2.x*0.25f, x2f = p2.y*0.25f;
    float4 u = bilin4(f1b, y2f, x2f, lane);
    float ss2 = wsum(u.x*u.x + u.y*u.y + u.z*u.z + u.w*u.w);
    float inv2 = 1.f / fmaxf(sqrtf(ss2), 1e-12f);
    u.x*=inv2; u.y*=inv2; u.z*=inv2; u.w*=inv2;
    split_store(u, g_Bh + (size_t)gid*Cc, g_Bl + (size_t)gid*Cc, lane);

    if (lane == 0) {
        g_qc0[gid] = bilin1(conf0 + (size_t)b*hc*wc, y0f, x0f);
        g_vp1[gid*2]   = (float)p1.x; g_vp1[gid*2+1] = (float)p1.y;
        g_vp2[gid*2]   = (float)p2.x; g_vp2[gid*2+1] = (float)p2.y;
    }
}

// ---------------- candidate scores (pos max + neg cols) + qconf + mask -------
__global__ void k_cand(const int* __restrict__ pos1, const float* __restrict__ conf1,
                       float* __restrict__ out_scores, float* __restrict__ out_mask,
                       float* __restrict__ out_qconf, int M) {
    __shared__ int soff[NCAND*2];
    for (int i = threadIdx.x; i < NCAND*2; i += blockDim.x) soff[i] = g_off[i];
    __syncthreads();

    int t = blockIdx.x*blockDim.x + threadIdx.x;
    int gid = t >> 5;
    if (gid >= BNc) return;
    int lane = t & 31;
    int b = gid / Nc, n = gid - b*Nc;
    int2 p1 = ((const int2*)pos1)[(size_t)b*M + n];
    const float* f1b = g_feat1T + (size_t)b*hc*wc*Cc;
    float4 q = ((const float4*)(g_vf0 + (size_t)gid*Cc))[lane];
    float* srow = out_scores + (size_t)gid*NCOLS;

    float best = -1e30f; int bestk = 0;
    for (int k = 0; k < NCAND; k++) {
        int dy = soff[2*k], dx = soff[2*k+1];
        float cy = (p1.x + dy)*0.25f, cx = (p1.y + dx)*0.25f;
        float4 fv = bilin4(f1b, cy, cx, lane);
        float dot = fv.x*q.x + fv.y*q.y + fv.z*q.z + fv.w*q.w;
        float ss  = fv.x*fv.x + fv.y*fv.y + fv.z*fv.z + fv.w*fv.w;
        #pragma unroll
        for (int o = 16; o; o >>= 1) {
            dot += __shfl_xor_sync(0xffffffffu, dot, o);
            ss  += __shfl_xor_sync(0xffffffffu, ss,  o);
        }
        float score = dot / fmaxf(sqrtf(ss), 1e-12f);
        if (k < Pc) { if (score > best) { best = score; bestk = k; } }
        else if (lane == 0) srow[1 + (k - Pc)] = score;
    }
    if (lane == 0) {
        srow[0] = best;
        int sy = p1.x + soff[2*bestk], sx = p1.y + soff[2*bestk+1];
        float q1 = bilin1(conf1 + (size_t)b*hc*wc, sy*0.25f, sx*0.25f);
        out_qconf[gid] = 0.5f*(g_qc0[gid] + q1);
        out_mask[gid]  = 1.0f;
    }
}

// ---------------- dscores: mma.sync split-bf16 GEMM 128x128 (K_eff=384) ------
// smem layout (bytes):
//   [0)      rpy/rpx/cpy/cpx float[128] each, rbb/cbb int[128]  (3072 B)
//   tiles: Ah, Al, Bh, Bl : 128 rows x 136 bf16 (pad 8) = 34816 B each
//   Ds slab: 32 x 132 f32 = 16896 B
#define LDT  136                 // bf16 leading dim of smem tiles
#define SM_ARR  0
#define SM_AH   3072
#define SM_AL   (SM_AH + 128*LDT*2)
#define SM_BH   (SM_AL + 128*LDT*2)
#define SM_BL   (SM_BH + 128*LDT*2)
#define SM_DS   (SM_BL + 128*LDT*2)
#define SM_TOTAL (SM_DS + 32*132*4)   // 159232

__device__ __forceinline__ void mma16816(float* c, const uint32_t* a, const uint32_t* b) {
    asm volatile(
        "mma.sync.aligned.m16n8k16.row.col.f32.bf16.bf16.f32 "
        "{%0,%1,%2,%3}, {%4,%5,%6,%7}, {%8,%9}, {%0,%1,%2,%3};"
        : "+f"(c[0]), "+f"(c[1]), "+f"(c[2]), "+f"(c[3])
        : "r"(a[0]), "r"(a[1]), "r"(a[2]), "r"(a[3]), "r"(b[0]), "r"(b[1]));
}

__global__ void __launch_bounds__(256, 1) k_gemm_mma(float* __restrict__ out_scores) {
    extern __shared__ char sm[];
    int tid = threadIdx.x, wid = tid >> 5, lane = tid & 31;
    int warp_m = wid & 3, warp_n = wid >> 2;       // 4 x 2 warps, warp tile 32x64
    int i0 = blockIdx.y * 128, j0 = blockIdx.x * 128;

    float* rpy = (float*)(sm + SM_ARR);
    float* rpx = rpy + 128;
    float* cpy = rpx + 128;
    float* cpx = cpy + 128;
    int*   rbb = (int*)(cpx + 128);
    int*   cbb = rbb + 128;
    float* Ds  = (float*)(sm + SM_DS);

    if (tid < 128) {
        int gi = i0 + tid;
        if (gi < BNc) { rpy[tid] = g_vp1[2*gi]; rpx[tid] = g_vp1[2*gi+1]; rbb[tid] = gi / Nc; }
        else          { rpy[tid] = 1e9f; rpx[tid] = 1e9f; rbb[tid] = -1; }
        int gj = j0 + tid;
        if (gj < BNc) { cpy[tid] = g_vp2[2*gj]; cpx[tid] = g_vp2[2*gj+1]; cbb[tid] = gj / Nc; }
        else          { cpy[tid] = -1e9f; cpx[tid] = -1e9f; cbb[tid] = -2; }
    }

    // load 4 tiles: 128 rows x 128 bf16 each, row stride LDT
    {
        int row8 = tid >> 4, c16 = tid & 15;     // 16 rows per 256-thread sweep
        #pragma unroll
        for (int tile = 0; tile < 4; tile++) {
            const __nv_bfloat16* g;
            char* base;
            int r0;
            if      (tile == 0) { g = g_Ah; r0 = i0; base = sm + SM_AH; }
            else if (tile == 1) { g = g_Al; r0 = i0; base = sm + SM_AL; }
            else if (tile == 2) { g = g_Bh; r0 = j0; base = sm + SM_BH; }
            else                { g = g_Bl; r0 = j0; base = sm + SM_BL; }
            #pragma unroll
            for (int it = 0; it < 8; it++) {
                int row = it * 16 + row8;
                *(uint4*)(base + row * (LDT*2) + c16 * 16) =
                    *(const uint4*)(g + (size_t)(r0 + row) * Cc + c16 * 8);
            }
        }
    }
    __syncthreads();

    float acc[2][8][4];
    #pragma unroll
    for (int mt = 0; mt < 2; mt++)
        #pragma unroll
        for (int nt = 0; nt < 8; nt++)
            #pragma unroll
            for (int q = 0; q < 4; q++) acc[mt][nt][q] = 0.f;

    const uint32_t* As32[3] = { (const uint32_t*)(sm + SM_AH), (const uint32_t*)(sm + SM_AH),
                                (const uint32_t*)(sm + SM_AL) };
    const uint32_t* Bs32[3] = { (const uint32_t*)(sm + SM_BH), (const uint32_t*)(sm + SM_BL),
                                (const uint32_t*)(sm + SM_BH) };
    const int LDW = LDT / 2;   // 68 32-bit words per row

    int qrow = lane >> 2, qk = lane & 3;
    #pragma unroll
    for (int pass = 0; pass < 3; pass++) {
        const uint32_t* A32 = As32[pass];
        const uint32_t* B32 = Bs32[pass];
        #pragma unroll
        for (int ks = 0; ks < 8; ks++) {
            int kw = ks * 8 + qk;
            uint32_t a[2][4], b[8][2];
            #pragma unroll
            for (int mt = 0; mt < 2; mt++) {
                int r = warp_m * 32 + mt * 16 + qrow;
                a[mt][0] = A32[r * LDW + kw];
                a[mt][1] = A32[(r + 8) * LDW + kw];
                a[mt][2] = A32[r * LDW + kw + 4];
                a[mt][3] = A32[(r + 8) * LDW + kw + 4];
            }
            #pragma unroll
            for (int nt = 0; nt < 8; nt++) {
                int n = warp_n * 64 + nt * 8 + qrow;
                b[nt][0] = B32[n * LDW + kw];
                b[nt][1] = B32[n * LDW + kw + 4];
            }
            #pragma unroll
            for (int mt = 0; mt < 2; mt++)
                #pragma unroll
                for (int nt = 0; nt < 8; nt++)
                    mma16816(acc[mt][nt], a[mt], b[nt]);
        }
    }
    __syncthreads();

    // epilogue: 4 slabs of 32 rows; stage in smem, masked coalesced write
    #pragma unroll
    for (int s = 0; s < 4; s++) {
        if (warp_m == s) {
            #pragma unroll
            for (int mt = 0; mt < 2; mt++) {
                int rr = mt * 16 + qrow;
                #pragma unroll
                for (int nt = 0; nt < 8; nt++) {
                    int cc = warp_n * 64 + nt * 8 + 2 * qk;
                    *(float2*)&Ds[rr * 132 + cc] =
                        make_float2(acc[mt][nt][0], acc[mt][nt][1]);
                    *(float2*)&Ds[(rr + 8) * 132 + cc] =
                        make_float2(acc[mt][nt][2], acc[mt][nt][3]);
                }
            }
        }
        __syncthreads();
        for (int rr = wid; rr < 32; rr += 8) {
            int lrow = s * 32 + rr;
            int gi = i0 + lrow;
            if (gi < BNc) {
                float py = rpy[lrow], px = rpx[lrow];
                int bi = rbb[lrow];
                float* orow = out_scores + (size_t)gi * NCOLS + 1 + NGc + j0;
                #pragma unroll
                for (int cb = 0; cb < 128; cb += 32) {
                    int j = cb + lane, gj = j0 + j;
                    if (gj < BNc) {
                        float v = Ds[rr * 132 + j];
                        float dy = cpy[j] - py, dx = cpx[j] - px;
                        if (bi == cbb[j] && dy*dy + dx*dx < 25.f) v = 0.f;
                        orow[j] = v;
                    }
                }
            }
        }
        __syncthreads();
    }
}

// ---------------- gt fill ----------------------------------------------------
__global__ void k_zero_gt(float4* __restrict__ gt4) {
    size_t n4 = (size_t)BNc * NCOLS / 4;
    size_t stride = (size_t)gridDim.x * blockDim.x;
    float4 z = make_float4(0.f, 0.f, 0.f, 0.f);
    for (size_t i = (size_t)blockIdx.x*blockDim.x + threadIdx.x; i < n4; i += stride)
        gt4[i] = z;
}
__global__ void k_ones_gt(float* __restrict__ gt) {
    int i = blockIdx.x*blockDim.x + threadIdx.x;
    if (i < BNc) gt[(size_t)i * NCOLS] = 1.f;
}

// ---------------- launch -----------------------------------------------------
extern "C" void kernel_launch(void* const* d_in, const int* in_sizes, int n_in,
                              void* d_out, int out_size) {
    const float* feat0 = (const float*)d_in[0];
    const float* feat1 = (const float*)d_in[1];
    const float* conf0 = (const float*)d_in[2];
    const float* conf1 = (const float*)d_in[3];
    const int*   pos0  = (const int*)d_in[4];
    const int*   pos1  = (const int*)d_in[5];
    int M = in_sizes[4] / (2 * Bc);   // 2500

    float* out        = (float*)d_out;
    float* out_scores = out;
    float* out_gt     = out + (size_t)BNc*NCOLS;
    float* out_mask   = out_gt + (size_t)BNc*NCOLS;
    float* out_qconf  = out_mask + BNc;

    cudaFuncSetAttribute(k_gemm_mma, cudaFuncAttributeMaxDynamicSharedMemorySize, SM_TOTAL);

    k_init_off<<<1, 1>>>();

    dim3 tb(32, 8), tg(wc/32, Cc/32, Bc*hc);
    k_transpose<<<tg, tb>>>(feat0, 0);
    k_transpose<<<tg, tb>>>(feat1, 1);

    k_prep<<<(BNc*32 + 255)/256, 256>>>(pos0, pos1, conf0, M);
    k_cand<<<(BNc*32 + 255)/256, 256>>>(pos1, conf1, out_scores, out_mask, out_qconf, M);

    dim3 gg(BN_PAD/128, BN_PAD/128);
    k_gemm_mma<<<gg, 256, SM_TOTAL>>>(out_scores);

    k_zero_gt<<<4096, 256>>>((float4*)out_gt);
    k_ones_gt<<<(BNc + 255)/256, 256>>>(out_gt);
}